// round 14
// baseline (speedup 1.0000x reference)
#include <cuda_runtime.h>
#include <cuda_fp16.h>
#include <mma.h>
#include <cstdint>
#include <math.h>

using namespace nvcuda;

// ---------------- static problem dims ----------------
#define BB    32
#define HH    56
#define WWD   56
#define CC    384
#define NTOK  (BB * HH * WWD)      // 100352
#define LL    49
#define NWIN  2048
#define C3    1152
#define NHEAD 12
#define HDIM  32

#define TK    32                    // GEMM K-chunk
#define SST   40                    // GEMM smem row stride (fp16)
#define TILEB (128 * SST * 2)       // 10240 B per tile
#define GSMEM (2 * 2 * TILEB)       // 40960 B dynamic (2 stages x {A,B})

// ---------------- scratch (device globals; no allocs allowed) ----------------
__device__ __half g_yh[(size_t)NTOK * CC];    // LN output fp16, window-ordered
__device__ __half g_qkvh[(size_t)NTOK * C3];  // qkv fp16, window-ordered
__device__ __half g_a[(size_t)NTOK * CC];     // attention out fp16
__device__ __half g_wi[(size_t)C3 * CC];      // w_in fp16
__device__ __half g_wo[(size_t)CC * CC];      // w_out fp16

// ---------------- K0: weight fp32 -> fp16 ----------------
__global__ void wconv_kernel(const float* __restrict__ w_in, const float* __restrict__ w_out) {
    int i = blockIdx.x * 256 + threadIdx.x;
    if (i < C3 * CC) g_wi[i] = __float2half(w_in[i]);
    if (i < CC * CC) g_wo[i] = __float2half(w_out[i]);
}

// ---------------- K1: LayerNorm + window partition -> fp16 ----------------
__global__ void ln_window_kernel(const float* __restrict__ x,
                                 const float* __restrict__ gamma,
                                 const float* __restrict__ beta) {
    int t = blockIdx.x;
    int tid = threadIdx.x;              // 128 threads
    const float* xin = x + (size_t)t * CC;
    float v0 = xin[tid], v1 = xin[tid + 128], v2 = xin[tid + 256];
    float s = v0 + v1 + v2;
    float s2 = v0 * v0 + v1 * v1 + v2 * v2;
    #pragma unroll
    for (int o = 16; o; o >>= 1) {
        s  += __shfl_down_sync(0xffffffffu, s, o);
        s2 += __shfl_down_sync(0xffffffffu, s2, o);
    }
    __shared__ float red[2][4];
    int wid = tid >> 5, lane = tid & 31;
    if (lane == 0) { red[0][wid] = s; red[1][wid] = s2; }
    __syncthreads();
    if (tid == 0) {
        float a = red[0][0] + red[0][1] + red[0][2] + red[0][3];
        float b = red[1][0] + red[1][1] + red[1][2] + red[1][3];
        float mu = a * (1.0f / CC);
        float var = b * (1.0f / CC) - mu * mu;
        red[0][0] = mu;
        red[1][0] = rsqrtf(var + 1e-5f);
    }
    __syncthreads();
    float mu = red[0][0], rs = red[1][0];

    int b_ = t / (HH * WWD);
    int n  = t % (HH * WWD);
    int h = n / WWD, w = n % WWD;
    int wi = h / 7, i = h % 7, wj = w / 7, j = w % 7;
    size_t row = (size_t)((b_ * 64 + wi * 8 + wj) * LL + i * 7 + j) * CC;
    #pragma unroll
    for (int q = 0; q < 3; q++) {
        int c = tid + q * 128;
        float v = (q == 0) ? v0 : (q == 1) ? v1 : v2;
        g_yh[row + c] = __float2half((v - mu) * rs * gamma[c] + beta[c]);
    }
}

// ---------------- cp.async helpers ----------------
__device__ __forceinline__ void cpa16(uint32_t saddr, const void* gptr) {
    asm volatile("cp.async.cg.shared.global [%0], [%1], 16;" :: "r"(saddr), "l"(gptr));
}

// ---------------- K2/K4: fp16 wmma GEMM, 128x128 block, 64x64 warp tile ----
// 128 threads / 4 warps; 2-stage cp.async; warp tile 64x64 (8 ldsm : 16 mma)
// EPI==0: A=g_yh, B=g_wi, N=1152, write g_qkvh fp16 (+bias)
// EPI==1: A=g_a,  B=g_wo, N=384,  write d_out fp32 (+bias, reverse, residual)
template <int EPI>
__global__ void __launch_bounds__(128) gemm_fp16_kernel(
        const float* __restrict__ bias,
        const float* __restrict__ resid,
        float* __restrict__ Cout) {
    extern __shared__ __align__(16) char smraw[];
    __half* stage[2][2];
    #pragma unroll
    for (int s = 0; s < 2; s++)
        #pragma unroll
        for (int t = 0; t < 2; t++)
            stage[s][t] = (__half*)(smraw + (s * 2 + t) * TILEB);

    const __half* A = (EPI == 0) ? g_yh : g_a;
    const __half* B = (EPI == 0) ? g_wi : g_wo;

    const int tid = threadIdx.x;        // 128 threads, 4 warps
    const int warp = tid >> 5;
    const int wm = warp >> 1;           // rows wm*64..+64
    const int wn = warp & 1;            // cols wn*64..+64
    const int n0 = blockIdx.x * 128;
    const int m0 = blockIdx.y * 128;

    wmma::fragment<wmma::accumulator, 16, 16, 16, float> acc[4][4];
    #pragma unroll
    for (int a = 0; a < 4; a++)
        #pragma unroll
        for (int b = 0; b < 4; b++) wmma::fill_fragment(acc[a][b], 0.0f);

    const int NCH = CC / TK;            // 12

    auto issue_copy = [&](int kc, int st) {
        const int k0 = kc * TK;
        const __half* ga = A + (size_t)(m0 + tid) * CC + k0;
        const __half* gb = B + (size_t)(n0 + tid) * CC + k0;
        uint32_t sa = (uint32_t)__cvta_generic_to_shared(stage[st][0] + tid * SST);
        uint32_t sb = (uint32_t)__cvta_generic_to_shared(stage[st][1] + tid * SST);
        #pragma unroll
        for (int s = 0; s < 4; s++) {
            cpa16(sa + s * 16, ga + s * 8);
            cpa16(sb + s * 16, gb + s * 8);
        }
        asm volatile("cp.async.commit_group;" ::: "memory");
    };

    issue_copy(0, 0);

    for (int kc = 0; kc < NCH; kc++) {
        const int cur = kc & 1;
        if (kc + 1 < NCH) {
            issue_copy(kc + 1, cur ^ 1);
            asm volatile("cp.async.wait_group 1;" ::: "memory");
        } else {
            asm volatile("cp.async.wait_group 0;" ::: "memory");
        }
        __syncthreads();
        const __half* sA = stage[cur][0];
        const __half* sB = stage[cur][1];
        #pragma unroll
        for (int kk = 0; kk < TK; kk += 16) {
            wmma::fragment<wmma::matrix_a, 16, 16, 16, __half, wmma::row_major> af[4];
            #pragma unroll
            for (int mi = 0; mi < 4; mi++)
                wmma::load_matrix_sync(af[mi], sA + (wm * 64 + mi * 16) * SST + kk, SST);
            #pragma unroll
            for (int ni = 0; ni < 4; ni++) {
                wmma::fragment<wmma::matrix_b, 16, 16, 16, __half, wmma::col_major> bf;
                wmma::load_matrix_sync(bf, sB + (wn * 64 + ni * 16) * SST + kk, SST);
                #pragma unroll
                for (int mi = 0; mi < 4; mi++)
                    wmma::mma_sync(acc[mi][ni], af[mi], bf, acc[mi][ni]);
            }
        }
        __syncthreads();
    }

    // epilogue: two 128x64 halves staged in smem (Cs 32768 B <= 40960)
    float* Cs = (float*)smraw;
    #pragma unroll
    for (int half = 0; half < 2; half++) {
        __syncthreads();
        if (wn == half) {
            #pragma unroll
            for (int mi = 0; mi < 4; mi++)
                #pragma unroll
                for (int ni = 0; ni < 4; ni++)
                    wmma::store_matrix_sync(Cs + (wm * 64 + mi * 16) * 64 + ni * 16,
                                            acc[mi][ni], 64, wmma::mem_row_major);
        }
        __syncthreads();
        if (EPI == 0) {
            // fp16 out, half2 stores: 4096 half2 / 128 thr = 32 each
            #pragma unroll
            for (int q = 0; q < 32; q++) {
                int idx = tid + q * 128;
                int r = idx >> 5, c2 = (idx & 31) * 2;
                int gcol = n0 + half * 64 + c2;
                float vx = Cs[r * 64 + c2]     + bias[gcol];
                float vy = Cs[r * 64 + c2 + 1] + bias[gcol + 1];
                *(__half2*)(g_qkvh + (size_t)(m0 + r) * C3 + gcol) =
                    __floats2half2_rn(vx, vy);
            }
        } else {
            #pragma unroll
            for (int q = 0; q < 64; q++) {
                int idx = tid + q * 128;
                int r = idx >> 6, c = idx & 63;
                int gcol = n0 + half * 64 + c;
                float val = Cs[idx] + bias[gcol];
                int m = m0 + r;
                int win = m / LL, l = m % LL;
                int b_ = win >> 6, wr = win & 63;
                int wi = wr >> 3, wj = wr & 7;
                int i = l / 7, j = l % 7;
                size_t orig = (size_t)b_ * (HH * WWD) + (size_t)(wi * 7 + i) * WWD + (wj * 7 + j);
                size_t off = orig * CC + gcol;
                Cout[off] = resid[off] + val;
            }
        }
    }
}

// ---------------- K3: attention via fp16 wmma, fp16 qkv, aliased smem -------
// layout (bytes): sQ 0..5120, sK 5120..10240, sV 10240..15360,
//                 sS 15360..32768 (64x68 fp32); sP aliases [0..9216) after S.
__global__ void attn_kernel() {
    __shared__ __align__(16) char sm[32768];
    __half* sQ = (__half*)sm;
    __half* sK = (__half*)(sm + 5120);
    __half* sV = (__half*)(sm + 10240);
    float*  sS = (float*)(sm + 15360);
    __half* sP = (__half*)sm;           // overlays Q/K once consumed
    int win = blockIdx.x;
    int head = blockIdx.y;
    int tid = threadIdx.x;              // 128 threads, 4 warps
    int warp = tid >> 5, lane = tid & 31;

    // zero V pad rows 49..63 (kill 0*garbage in P.V)
    for (int idx = tid; idx < 15 * 20; idx += 128)
        ((uint32_t*)(sV + 49 * 40))[idx] = 0u;

    const __half* base = g_qkvh + (size_t)win * LL * C3 + head * HDIM;
    const __half2 sc2 = __float2half2_rn(0.17677669529663687f);  // 1/sqrt(32)
    for (int idx = tid; idx < LL * 4; idx += 128) {
        int l = idx >> 2, d8 = (idx & 3) * 8;
        const __half* p = base + (size_t)l * C3 + d8;
        uint4 q4 = *(const uint4*)(p);
        uint4 k4 = *(const uint4*)(p + 384);
        uint4 v4 = *(const uint4*)(p + 768);
        __half2* qh = (__half2*)&q4;
        #pragma unroll
        for (int e = 0; e < 4; e++) qh[e] = __hmul2(qh[e], sc2);
        *(uint4*)(sQ + l * 40 + d8) = q4;
        *(uint4*)(sK + l * 40 + d8) = k4;
        *(uint4*)(sV + l * 40 + d8) = v4;
    }
    __syncthreads();

    // ---- S = Q.K^T : warp w -> rows 16w..16w+15 ----
    {
        wmma::fragment<wmma::accumulator, 16, 16, 16, float> sacc[4];
        #pragma unroll
        for (int n = 0; n < 4; n++) wmma::fill_fragment(sacc[n], 0.0f);
        #pragma unroll
        for (int k = 0; k < 2; k++) {
            wmma::fragment<wmma::matrix_a, 16, 16, 16, __half, wmma::row_major> af;
            wmma::load_matrix_sync(af, sQ + warp * 16 * 40 + k * 16, 40);
            #pragma unroll
            for (int n = 0; n < 4; n++) {
                wmma::fragment<wmma::matrix_b, 16, 16, 16, __half, wmma::col_major> bf;
                wmma::load_matrix_sync(bf, sK + n * 16 * 40 + k * 16, 40);
                wmma::mma_sync(sacc[n], af, bf, sacc[n]);
            }
        }
        #pragma unroll
        for (int n = 0; n < 4; n++)
            wmma::store_matrix_sync(sS + warp * 16 * 68 + n * 16, sacc[n], 68, wmma::mem_row_major);
    }
    __syncthreads();

    // zero P fully (aliases Q/K, now dead): 64*72*2/4 = 2304 words
    #pragma unroll
    for (int q = 0; q < 18; q++) ((uint32_t*)sP)[tid + q * 128] = 0u;
    __syncthreads();

    // ---- softmax rows 0..48 (cols 0..48), write P fp16 ----
    bool has2 = lane < 17;
    for (int i = warp; i < LL; i += 4) {
        float a = sS[i * 68 + lane];
        float b = has2 ? sS[i * 68 + lane + 32] : -3.0e38f;
        float m = fmaxf(a, b);
        #pragma unroll
        for (int o = 16; o; o >>= 1) m = fmaxf(m, __shfl_xor_sync(0xffffffffu, m, o));
        float e0 = __expf(a - m);
        float e1 = has2 ? __expf(b - m) : 0.f;
        float sm_ = e0 + e1;
        #pragma unroll
        for (int o = 16; o; o >>= 1) sm_ += __shfl_xor_sync(0xffffffffu, sm_, o);
        float inv = 1.0f / sm_;
        sP[i * 72 + lane] = __float2half(e0 * inv);
        if (has2) sP[i * 72 + lane + 32] = __float2half(e1 * inv);
    }
    __syncthreads();

    // ---- O = P.V : warp w -> rows 16w..16w+15; stage out via sS (ldm 36) ----
    {
        wmma::fragment<wmma::accumulator, 16, 16, 16, float> oacc[2];
        #pragma unroll
        for (int n = 0; n < 2; n++) wmma::fill_fragment(oacc[n], 0.0f);
        #pragma unroll
        for (int k = 0; k < 4; k++) {
            wmma::fragment<wmma::matrix_a, 16, 16, 16, __half, wmma::row_major> pf;
            wmma::load_matrix_sync(pf, sP + warp * 16 * 72 + k * 16, 72);
            #pragma unroll
            for (int n = 0; n < 2; n++) {
                wmma::fragment<wmma::matrix_b, 16, 16, 16, __half, wmma::row_major> vf;
                wmma::load_matrix_sync(vf, sV + k * 16 * 40 + n * 16, 40);
                wmma::mma_sync(oacc[n], pf, vf, oacc[n]);
            }
        }
        #pragma unroll
        for (int n = 0; n < 2; n++)
            wmma::store_matrix_sync(sS + warp * 16 * 36 + n * 16, oacc[n], 36, wmma::mem_row_major);
    }
    __syncthreads();

    // ---- write O rows 0..48 ----
    for (int idx = tid; idx < LL * HDIM; idx += 128) {
        int row = idx >> 5, col = idx & 31;
        g_a[((size_t)win * LL + row) * CC + head * HDIM + col] =
            __float2half(sS[row * 36 + col]);
    }
}

// ---------------- launch ----------------
extern "C" void kernel_launch(void* const* d_in, const int* in_sizes, int n_in,
                              void* d_out, int out_size) {
    const float* x     = (const float*)d_in[0];
    const float* gamma = (const float*)d_in[1];
    const float* beta  = (const float*)d_in[2];
    const float* w_in  = (const float*)d_in[3];
    const float* b_in  = (const float*)d_in[4];
    const float* w_out = (const float*)d_in[5];
    const float* b_out = (const float*)d_in[6];
    float* out = (float*)d_out;

    cudaFuncSetAttribute(gemm_fp16_kernel<0>,
                         cudaFuncAttributeMaxDynamicSharedMemorySize, GSMEM);
    cudaFuncSetAttribute(gemm_fp16_kernel<1>,
                         cudaFuncAttributeMaxDynamicSharedMemorySize, GSMEM);

    wconv_kernel<<<(C3 * CC + 255) / 256, 256>>>(w_in, w_out);
    ln_window_kernel<<<NTOK, 128>>>(x, gamma, beta);
    gemm_fp16_kernel<0><<<dim3(C3 / 128, NTOK / 128), 128, GSMEM>>>(b_in, nullptr, nullptr);
    attn_kernel<<<dim3(NWIN, NHEAD), 128>>>();
    gemm_fp16_kernel<1><<<dim3(CC / 128, NTOK / 128), 128, GSMEM>>>(b_out, x, out);
}

// round 15
// speedup vs baseline: 1.1961x; 1.1961x over previous
#include <cuda_runtime.h>
#include <cuda_fp16.h>
#include <mma.h>
#include <cstdint>
#include <math.h>

using namespace nvcuda;

// ---------------- static problem dims ----------------
#define BB    32
#define HH    56
#define WWD   56
#define CC    384
#define NTOK  (BB * HH * WWD)      // 100352
#define LL    49
#define NWIN  2048
#define C3    1152
#define NHEAD 12
#define HDIM  32

#define TK    32                    // GEMM K-chunk
#define SST   40                    // GEMM smem row stride (fp16)
#define TILEB (128 * SST * 2)       // 10240 B per tile
#define NSTG  3                     // pipeline stages
#define GSMEM (NSTG * 2 * TILEB)    // 61440 B dynamic

// ---------------- scratch (device globals; no allocs allowed) ----------------
__device__ __half g_yh[(size_t)NTOK * CC];    // LN output fp16, window-ordered
__device__ __half g_qkvh[(size_t)NTOK * C3];  // qkv fp16, window-ordered
__device__ __half g_a[(size_t)NTOK * CC];     // attention out fp16
__device__ __half g_wi[(size_t)C3 * CC];      // w_in fp16
__device__ __half g_wo[(size_t)CC * CC];      // w_out fp16

// ---------------- K0: weight fp32 -> fp16 ----------------
__global__ void wconv_kernel(const float* __restrict__ w_in, const float* __restrict__ w_out) {
    int i = blockIdx.x * 256 + threadIdx.x;
    if (i < C3 * CC) g_wi[i] = __float2half(w_in[i]);
    if (i < CC * CC) g_wo[i] = __float2half(w_out[i]);
}

// ---------------- K1: LayerNorm + window partition -> fp16 ----------------
__global__ void ln_window_kernel(const float* __restrict__ x,
                                 const float* __restrict__ gamma,
                                 const float* __restrict__ beta) {
    int t = blockIdx.x;
    int tid = threadIdx.x;              // 128 threads
    const float* xin = x + (size_t)t * CC;
    float v0 = xin[tid], v1 = xin[tid + 128], v2 = xin[tid + 256];
    float s = v0 + v1 + v2;
    float s2 = v0 * v0 + v1 * v1 + v2 * v2;
    #pragma unroll
    for (int o = 16; o; o >>= 1) {
        s  += __shfl_down_sync(0xffffffffu, s, o);
        s2 += __shfl_down_sync(0xffffffffu, s2, o);
    }
    __shared__ float red[2][4];
    int wid = tid >> 5, lane = tid & 31;
    if (lane == 0) { red[0][wid] = s; red[1][wid] = s2; }
    __syncthreads();
    if (tid == 0) {
        float a = red[0][0] + red[0][1] + red[0][2] + red[0][3];
        float b = red[1][0] + red[1][1] + red[1][2] + red[1][3];
        float mu = a * (1.0f / CC);
        float var = b * (1.0f / CC) - mu * mu;
        red[0][0] = mu;
        red[1][0] = rsqrtf(var + 1e-5f);
    }
    __syncthreads();
    float mu = red[0][0], rs = red[1][0];

    int b_ = t / (HH * WWD);
    int n  = t % (HH * WWD);
    int h = n / WWD, w = n % WWD;
    int wi = h / 7, i = h % 7, wj = w / 7, j = w % 7;
    size_t row = (size_t)((b_ * 64 + wi * 8 + wj) * LL + i * 7 + j) * CC;
    #pragma unroll
    for (int q = 0; q < 3; q++) {
        int c = tid + q * 128;
        float v = (q == 0) ? v0 : (q == 1) ? v1 : v2;
        g_yh[row + c] = __float2half((v - mu) * rs * gamma[c] + beta[c]);
    }
}

// ---------------- cp.async helpers ----------------
__device__ __forceinline__ void cpa16(uint32_t saddr, const void* gptr) {
    asm volatile("cp.async.cg.shared.global [%0], [%1], 16;" :: "r"(saddr), "l"(gptr));
}

// ---------------- K2/K4: fp16 wmma GEMM, 128x128, 256 thr, 3-stage cp.async -
// EPI==0: A=g_yh, B=g_wi, N=1152, write g_qkvh fp16 (+bias)
// EPI==1: A=g_a,  B=g_wo, N=384,  write d_out fp32 (+bias, reverse, residual)
template <int EPI>
__global__ void __launch_bounds__(256, 2) gemm_fp16_kernel(
        const float* __restrict__ bias,
        const float* __restrict__ resid,
        float* __restrict__ Cout) {
    extern __shared__ __align__(16) char smraw[];
    __half* stage[NSTG][2];
    #pragma unroll
    for (int s = 0; s < NSTG; s++)
        #pragma unroll
        for (int t = 0; t < 2; t++)
            stage[s][t] = (__half*)(smraw + (s * 2 + t) * TILEB);

    const __half* A = (EPI == 0) ? g_yh : g_a;
    const __half* B = (EPI == 0) ? g_wi : g_wo;

    const int tid = threadIdx.x;        // 256 threads, 8 warps
    const int warp = tid >> 5;
    const int wm = warp >> 1;           // rows wm*32..+32
    const int wn = warp & 1;            // cols wn*64..+64
    const int n0 = blockIdx.x * 128;
    const int m0 = blockIdx.y * 128;

    const int r0 = tid >> 1, s0 = (tid & 1) * 2;

    wmma::fragment<wmma::accumulator, 16, 16, 16, float> acc[2][4];
    #pragma unroll
    for (int a = 0; a < 2; a++)
        #pragma unroll
        for (int b = 0; b < 4; b++) wmma::fill_fragment(acc[a][b], 0.0f);

    const int NCH = CC / TK;            // 12

    auto issue_copy = [&](int kc, int st) {
        const int k0 = kc * TK;
        const __half* ga = A + (size_t)(m0 + r0) * CC + k0;
        const __half* gb = B + (size_t)(n0 + r0) * CC + k0;
        uint32_t sa = (uint32_t)__cvta_generic_to_shared(stage[st][0] + r0 * SST + s0 * 8);
        cpa16(sa, ga + s0 * 8);
        cpa16(sa + 16, ga + s0 * 8 + 8);
        uint32_t sb = (uint32_t)__cvta_generic_to_shared(stage[st][1] + r0 * SST + s0 * 8);
        cpa16(sb, gb + s0 * 8);
        cpa16(sb + 16, gb + s0 * 8 + 8);
        asm volatile("cp.async.commit_group;" ::: "memory");
    };

    issue_copy(0, 0);
    issue_copy(1, 1);

    for (int kc = 0; kc < NCH; kc++) {
        const int cur = kc % NSTG;
        if (kc + 2 < NCH) {
            issue_copy(kc + 2, (kc + 2) % NSTG);
            asm volatile("cp.async.wait_group 2;" ::: "memory");
        } else if (kc + 1 < NCH) {
            asm volatile("cp.async.wait_group 1;" ::: "memory");
        } else {
            asm volatile("cp.async.wait_group 0;" ::: "memory");
        }
        __syncthreads();
        const __half* sA = stage[cur][0];
        const __half* sB = stage[cur][1];
        #pragma unroll
        for (int kk = 0; kk < TK; kk += 16) {
            wmma::fragment<wmma::matrix_a, 16, 16, 16, __half, wmma::row_major> af[2];
            wmma::fragment<wmma::matrix_b, 16, 16, 16, __half, wmma::col_major> bf[4];
            #pragma unroll
            for (int mi = 0; mi < 2; mi++)
                wmma::load_matrix_sync(af[mi], sA + (wm * 32 + mi * 16) * SST + kk, SST);
            #pragma unroll
            for (int ni = 0; ni < 4; ni++)
                wmma::load_matrix_sync(bf[ni], sB + (wn * 64 + ni * 16) * SST + kk, SST);
            #pragma unroll
            for (int mi = 0; mi < 2; mi++)
                #pragma unroll
                for (int ni = 0; ni < 4; ni++)
                    wmma::mma_sync(acc[mi][ni], af[mi], bf[ni], acc[mi][ni]);
        }
        __syncthreads();
    }

    float* Cs = (float*)smraw;          // 32768 B <= 61440
    #pragma unroll
    for (int half = 0; half < 2; half++) {
        __syncthreads();
        if (wn == half) {
            #pragma unroll
            for (int mi = 0; mi < 2; mi++)
                #pragma unroll
                for (int ni = 0; ni < 4; ni++)
                    wmma::store_matrix_sync(Cs + (wm * 32 + mi * 16) * 64 + ni * 16,
                                            acc[mi][ni], 64, wmma::mem_row_major);
        }
        __syncthreads();
        if (EPI == 0) {
            #pragma unroll
            for (int q = 0; q < 16; q++) {
                int idx = tid + q * 256;        // 4096 half2 positions
                int r = idx >> 5, c2 = (idx & 31) * 2;
                int gcol = n0 + half * 64 + c2;
                float vx = Cs[r * 64 + c2]     + bias[gcol];
                float vy = Cs[r * 64 + c2 + 1] + bias[gcol + 1];
                *(__half2*)(g_qkvh + (size_t)(m0 + r) * C3 + gcol) =
                    __floats2half2_rn(vx, vy);
            }
        } else {
            #pragma unroll
            for (int q = 0; q < 32; q++) {
                int idx = tid + q * 256;
                int r = idx >> 6, c = idx & 63;
                int gcol = n0 + half * 64 + c;
                float val = Cs[idx] + bias[gcol];
                int m = m0 + r;
                int win = m / LL, l = m % LL;
                int b_ = win >> 6, wr = win & 63;
                int wi = wr >> 3, wj = wr & 7;
                int i = l / 7, j = l % 7;
                size_t orig = (size_t)b_ * (HH * WWD) + (size_t)(wi * 7 + i) * WWD + (wj * 7 + j);
                size_t off = orig * CC + gcol;
                Cout[off] = resid[off] + val;
            }
        }
    }
}

// ---------------- K3: attention via fp16 wmma, fp16 qkv, aliased smem -------
// layout (bytes): sQ 0..5120, sK 5120..10240, sV 10240..15360,
//                 sS 15360..32768 (64x68 fp32); sP aliases [0..9216) after S.
__global__ void attn_kernel() {
    __shared__ __align__(16) char sm[32768];
    __half* sQ = (__half*)sm;
    __half* sK = (__half*)(sm + 5120);
    __half* sV = (__half*)(sm + 10240);
    float*  sS = (float*)(sm + 15360);
    __half* sP = (__half*)sm;           // overlays Q/K once consumed
    int win = blockIdx.x;
    int head = blockIdx.y;
    int tid = threadIdx.x;              // 128 threads, 4 warps
    int warp = tid >> 5, lane = tid & 31;

    // zero V pad rows 49..63 (kill 0*garbage in P.V)
    for (int idx = tid; idx < 15 * 20; idx += 128)
        ((uint32_t*)(sV + 49 * 40))[idx] = 0u;

    const __half* base = g_qkvh + (size_t)win * LL * C3 + head * HDIM;
    const __half2 sc2 = __float2half2_rn(0.17677669529663687f);  // 1/sqrt(32)
    for (int idx = tid; idx < LL * 4; idx += 128) {
        int l = idx >> 2, d8 = (idx & 3) * 8;
        const __half* p = base + (size_t)l * C3 + d8;
        uint4 q4 = *(const uint4*)(p);
        uint4 k4 = *(const uint4*)(p + 384);
        uint4 v4 = *(const uint4*)(p + 768);
        __half2* qh = (__half2*)&q4;
        #pragma unroll
        for (int e = 0; e < 4; e++) qh[e] = __hmul2(qh[e], sc2);
        *(uint4*)(sQ + l * 40 + d8) = q4;
        *(uint4*)(sK + l * 40 + d8) = k4;
        *(uint4*)(sV + l * 40 + d8) = v4;
    }
    __syncthreads();

    // ---- S = Q.K^T : warp w -> rows 16w..16w+15 ----
    {
        wmma::fragment<wmma::accumulator, 16, 16, 16, float> sacc[4];
        #pragma unroll
        for (int n = 0; n < 4; n++) wmma::fill_fragment(sacc[n], 0.0f);
        #pragma unroll
        for (int k = 0; k < 2; k++) {
            wmma::fragment<wmma::matrix_a, 16, 16, 16, __half, wmma::row_major> af;
            wmma::load_matrix_sync(af, sQ + warp * 16 * 40 + k * 16, 40);
            #pragma unroll
            for (int n = 0; n < 4; n++) {
                wmma::fragment<wmma::matrix_b, 16, 16, 16, __half, wmma::col_major> bf;
                wmma::load_matrix_sync(bf, sK + n * 16 * 40 + k * 16, 40);
                wmma::mma_sync(sacc[n], af, bf, sacc[n]);
            }
        }
        #pragma unroll
        for (int n = 0; n < 4; n++)
            wmma::store_matrix_sync(sS + warp * 16 * 68 + n * 16, sacc[n], 68, wmma::mem_row_major);
    }
    __syncthreads();

    // zero P fully (aliases Q/K, now dead): 64*72*2/4 = 2304 words
    #pragma unroll
    for (int q = 0; q < 18; q++) ((uint32_t*)sP)[tid + q * 128] = 0u;
    __syncthreads();

    // ---- softmax rows 0..48 (cols 0..48), write P fp16 ----
    bool has2 = lane < 17;
    for (int i = warp; i < LL; i += 4) {
        float a = sS[i * 68 + lane];
        float b = has2 ? sS[i * 68 + lane + 32] : -3.0e38f;
        float m = fmaxf(a, b);
        #pragma unroll
        for (int o = 16; o; o >>= 1) m = fmaxf(m, __shfl_xor_sync(0xffffffffu, m, o));
        float e0 = __expf(a - m);
        float e1 = has2 ? __expf(b - m) : 0.f;
        float sm_ = e0 + e1;
        #pragma unroll
        for (int o = 16; o; o >>= 1) sm_ += __shfl_xor_sync(0xffffffffu, sm_, o);
        float inv = 1.0f / sm_;
        sP[i * 72 + lane] = __float2half(e0 * inv);
        if (has2) sP[i * 72 + lane + 32] = __float2half(e1 * inv);
    }
    __syncthreads();

    // ---- O = P.V : warp w -> rows 16w..16w+15; stage out via sS (ldm 36) ----
    {
        wmma::fragment<wmma::accumulator, 16, 16, 16, float> oacc[2];
        #pragma unroll
        for (int n = 0; n < 2; n++) wmma::fill_fragment(oacc[n], 0.0f);
        #pragma unroll
        for (int k = 0; k < 4; k++) {
            wmma::fragment<wmma::matrix_a, 16, 16, 16, __half, wmma::row_major> pf;
            wmma::load_matrix_sync(pf, sP + warp * 16 * 72 + k * 16, 72);
            #pragma unroll
            for (int n = 0; n < 2; n++) {
                wmma::fragment<wmma::matrix_b, 16, 16, 16, __half, wmma::row_major> vf;
                wmma::load_matrix_sync(vf, sV + k * 16 * 40 + n * 16, 40);
                wmma::mma_sync(oacc[n], pf, vf, oacc[n]);
            }
        }
        #pragma unroll
        for (int n = 0; n < 2; n++)
            wmma::store_matrix_sync(sS + warp * 16 * 36 + n * 16, oacc[n], 36, wmma::mem_row_major);
    }
    __syncthreads();

    // ---- write O rows 0..48 ----
    for (int idx = tid; idx < LL * HDIM; idx += 128) {
        int row = idx >> 5, col = idx & 31;
        g_a[((size_t)win * LL + row) * CC + head * HDIM + col] =
            __float2half(sS[row * 36 + col]);
    }
}

// ---------------- launch ----------------
extern "C" void kernel_launch(void* const* d_in, const int* in_sizes, int n_in,
                              void* d_out, int out_size) {
    const float* x     = (const float*)d_in[0];
    const float* gamma = (const float*)d_in[1];
    const float* beta  = (const float*)d_in[2];
    const float* w_in  = (const float*)d_in[3];
    const float* b_in  = (const float*)d_in[4];
    const float* w_out = (const float*)d_in[5];
    const float* b_out = (const float*)d_in[6];
    float* out = (float*)d_out;

    cudaFuncSetAttribute(gemm_fp16_kernel<0>,
                         cudaFuncAttributeMaxDynamicSharedMemorySize, GSMEM);
    cudaFuncSetAttribute(gemm_fp16_kernel<1>,
                         cudaFuncAttributeMaxDynamicSharedMemorySize, GSMEM);

    wconv_kernel<<<(C3 * CC + 255) / 256, 256>>>(w_in, w_out);
    ln_window_kernel<<<NTOK, 128>>>(x, gamma, beta);
    gemm_fp16_kernel<0><<<dim3(C3 / 128, NTOK / 128), 256, GSMEM>>>(b_in, nullptr, nullptr);
    attn_kernel<<<dim3(NWIN, NHEAD), 128>>>();
    gemm_fp16_kernel<1><<<dim3(CC / 128, NTOK / 128), 256, GSMEM>>>(b_out, x, out);
}

// round 16
// speedup vs baseline: 1.3987x; 1.1694x over previous
#include <cuda_runtime.h>
#include <cuda_fp16.h>
#include <mma.h>
#include <cstdint>
#include <math.h>

using namespace nvcuda;

// ---------------- static problem dims ----------------
#define BB    32
#define HH    56
#define WWD   56
#define CC    384
#define NTOK  (BB * HH * WWD)      // 100352
#define LL    49
#define NWIN  2048
#define C3    1152
#define NHEAD 12
#define HDIM  32

#define TK    32                    // GEMM K-chunk
#define SST   40                    // GEMM smem row stride (fp16)
#define TILEB (128 * SST * 2)       // 10240 B per tile
#define NSTG  3                     // pipeline stages
#define GSMEM (128 * 132 * 4)       // 67584 B dyn (>= NSTG*2*TILEB = 61440)
#define ASMEM (2 * 32768)           // attn dyn smem: two 32KB head regions

// ---------------- scratch (device globals; no allocs allowed) ----------------
__device__ __half g_yh[(size_t)NTOK * CC];    // LN output fp16, window-ordered
__device__ __half g_qkvh[(size_t)NTOK * C3];  // qkv fp16, window-ordered
__device__ __half g_a[(size_t)NTOK * CC];     // attention out fp16
__device__ __half g_wi[(size_t)C3 * CC];      // w_in fp16
__device__ __half g_wo[(size_t)CC * CC];      // w_out fp16

// ---------------- K0: weight fp32 -> fp16 ----------------
__global__ void wconv_kernel(const float* __restrict__ w_in, const float* __restrict__ w_out) {
    int i = blockIdx.x * 256 + threadIdx.x;
    if (i < C3 * CC) g_wi[i] = __float2half(w_in[i]);
    if (i < CC * CC) g_wo[i] = __float2half(w_out[i]);
}

// ---------------- K1: LayerNorm + window partition -> fp16 ----------------
__global__ void ln_window_kernel(const float* __restrict__ x,
                                 const float* __restrict__ gamma,
                                 const float* __restrict__ beta) {
    int t = blockIdx.x;
    int tid = threadIdx.x;              // 128 threads
    const float* xin = x + (size_t)t * CC;
    float v0 = xin[tid], v1 = xin[tid + 128], v2 = xin[tid + 256];
    float s = v0 + v1 + v2;
    float s2 = v0 * v0 + v1 * v1 + v2 * v2;
    #pragma unroll
    for (int o = 16; o; o >>= 1) {
        s  += __shfl_down_sync(0xffffffffu, s, o);
        s2 += __shfl_down_sync(0xffffffffu, s2, o);
    }
    __shared__ float red[2][4];
    int wid = tid >> 5, lane = tid & 31;
    if (lane == 0) { red[0][wid] = s; red[1][wid] = s2; }
    __syncthreads();
    if (tid == 0) {
        float a = red[0][0] + red[0][1] + red[0][2] + red[0][3];
        float b = red[1][0] + red[1][1] + red[1][2] + red[1][3];
        float mu = a * (1.0f / CC);
        float var = b * (1.0f / CC) - mu * mu;
        red[0][0] = mu;
        red[1][0] = rsqrtf(var + 1e-5f);
    }
    __syncthreads();
    float mu = red[0][0], rs = red[1][0];

    int b_ = t / (HH * WWD);
    int n  = t % (HH * WWD);
    int h = n / WWD, w = n % WWD;
    int wi = h / 7, i = h % 7, wj = w / 7, j = w % 7;
    size_t row = (size_t)((b_ * 64 + wi * 8 + wj) * LL + i * 7 + j) * CC;
    #pragma unroll
    for (int q = 0; q < 3; q++) {
        int c = tid + q * 128;
        float v = (q == 0) ? v0 : (q == 1) ? v1 : v2;
        g_yh[row + c] = __float2half((v - mu) * rs * gamma[c] + beta[c]);
    }
}

// ---------------- cp.async helpers ----------------
__device__ __forceinline__ void cpa16(uint32_t saddr, const void* gptr) {
    asm volatile("cp.async.cg.shared.global [%0], [%1], 16;" :: "r"(saddr), "l"(gptr));
}

// ---------------- K2/K4: fp16 wmma GEMM, 128x128, 3-stage, 1 barrier/chunk --
// EPI==0: A=g_yh, B=g_wi, N=1152, write g_qkvh fp16 (+bias)
// EPI==1: A=g_a,  B=g_wo, N=384,  write d_out fp32 (+bias, reverse, residual)
template <int EPI>
__global__ void __launch_bounds__(256, 2) gemm_fp16_kernel(
        const float* __restrict__ bias,
        const float* __restrict__ resid,
        float* __restrict__ Cout) {
    extern __shared__ __align__(16) char smraw[];
    __half* stage[NSTG][2];
    #pragma unroll
    for (int s = 0; s < NSTG; s++)
        #pragma unroll
        for (int t = 0; t < 2; t++)
            stage[s][t] = (__half*)(smraw + (s * 2 + t) * TILEB);

    const __half* A = (EPI == 0) ? g_yh : g_a;
    const __half* B = (EPI == 0) ? g_wi : g_wo;

    const int tid = threadIdx.x;        // 256 threads, 8 warps
    const int warp = tid >> 5;
    const int wm = warp >> 1;           // rows wm*32..+32
    const int wn = warp & 1;            // cols wn*64..+64
    const int n0 = blockIdx.x * 128;
    const int m0 = blockIdx.y * 128;

    const int r0 = tid >> 1, s0 = (tid & 1) * 2;

    wmma::fragment<wmma::accumulator, 16, 16, 16, float> acc[2][4];
    #pragma unroll
    for (int a = 0; a < 2; a++)
        #pragma unroll
        for (int b = 0; b < 4; b++) wmma::fill_fragment(acc[a][b], 0.0f);

    const int NCH = CC / TK;            // 12

    auto issue_copy = [&](int kc, int st) {
        const int k0 = kc * TK;
        const __half* ga = A + (size_t)(m0 + r0) * CC + k0;
        const __half* gb = B + (size_t)(n0 + r0) * CC + k0;
        uint32_t sa = (uint32_t)__cvta_generic_to_shared(stage[st][0] + r0 * SST + s0 * 8);
        cpa16(sa, ga + s0 * 8);
        cpa16(sa + 16, ga + s0 * 8 + 8);
        uint32_t sb = (uint32_t)__cvta_generic_to_shared(stage[st][1] + r0 * SST + s0 * 8);
        cpa16(sb, gb + s0 * 8);
        cpa16(sb + 16, gb + s0 * 8 + 8);
        asm volatile("cp.async.commit_group;" ::: "memory");
    };

    issue_copy(0, 0);
    issue_copy(1, 1);

    for (int kc = 0; kc < NCH; kc++) {
        const int cur = kc % NSTG;
        if (kc + 1 < NCH) {
            asm volatile("cp.async.wait_group 1;" ::: "memory");
        } else {
            asm volatile("cp.async.wait_group 0;" ::: "memory");
        }
        __syncthreads();                // single barrier per chunk
        // safe: stage (kc+2)%3 was last read in chunk kc-1, all warps past barrier
        if (kc + 2 < NCH) issue_copy(kc + 2, (kc + 2) % NSTG);
        const __half* sA = stage[cur][0];
        const __half* sB = stage[cur][1];
        #pragma unroll
        for (int kk = 0; kk < TK; kk += 16) {
            wmma::fragment<wmma::matrix_a, 16, 16, 16, __half, wmma::row_major> af[2];
            wmma::fragment<wmma::matrix_b, 16, 16, 16, __half, wmma::col_major> bf[4];
            #pragma unroll
            for (int mi = 0; mi < 2; mi++)
                wmma::load_matrix_sync(af[mi], sA + (wm * 32 + mi * 16) * SST + kk, SST);
            #pragma unroll
            for (int ni = 0; ni < 4; ni++)
                wmma::load_matrix_sync(bf[ni], sB + (wn * 64 + ni * 16) * SST + kk, SST);
            #pragma unroll
            for (int mi = 0; mi < 2; mi++)
                #pragma unroll
                for (int ni = 0; ni < 4; ni++)
                    wmma::mma_sync(acc[mi][ni], af[mi], bf[ni], acc[mi][ni]);
        }
    }

    // ---- epilogue: single pass, Cs 128x132 fp32 ----
    float* Cs = (float*)smraw;
    __syncthreads();                    // all MMAs done before overwriting stages
    #pragma unroll
    for (int mi = 0; mi < 2; mi++)
        #pragma unroll
        for (int ni = 0; ni < 4; ni++)
            wmma::store_matrix_sync(Cs + (wm * 32 + mi * 16) * 132 + wn * 64 + ni * 16,
                                    acc[mi][ni], 132, wmma::mem_row_major);
    __syncthreads();
    if (EPI == 0) {
        // 128x128 fp16 out: 8192 half2 / 256 thr = 32 each
        #pragma unroll
        for (int q = 0; q < 32; q++) {
            int idx = tid + q * 256;
            int r = idx >> 6, c2 = (idx & 63) * 2;
            int gcol = n0 + c2;
            float vx = Cs[r * 132 + c2]     + bias[gcol];
            float vy = Cs[r * 132 + c2 + 1] + bias[gcol + 1];
            *(__half2*)(g_qkvh + (size_t)(m0 + r) * C3 + gcol) =
                __floats2half2_rn(vx, vy);
        }
    } else {
        #pragma unroll
        for (int q = 0; q < 64; q++) {
            int idx = tid + q * 256;
            int r = idx >> 7, c = idx & 127;
            int gcol = n0 + c;
            float val = Cs[r * 132 + c] + bias[gcol];
            int m = m0 + r;
            int win = m / LL, l = m % LL;
            int b_ = win >> 6, wr = win & 63;
            int wi = wr >> 3, wj = wr & 7;
            int i = l / 7, j = l % 7;
            size_t orig = (size_t)b_ * (HH * WWD) + (size_t)(wi * 7 + i) * WWD + (wj * 7 + j);
            size_t off = orig * CC + gcol;
            Cout[off] = resid[off] + val;
        }
    }
}

// ---------------- K3: attention, 2 heads per CTA (256 thr), aliased smem ----
// per-head region (32768 B): sQ 0..5120, sK 5120..10240, sV 10240..15360,
//   sS 15360..32768 (64x68 fp32); sP aliases [0..9216) after S is built.
__global__ void attn_kernel() {
    extern __shared__ __align__(16) char smbase[];
    int tid = threadIdx.x;              // 256 threads, 8 warps
    int half_ = tid >> 7;               // 0 or 1: which head
    int t = tid & 127;                  // tid within half
    int lw = (tid >> 5) & 3;            // warp within half
    int lane = tid & 31;
    char* sm = smbase + half_ * 32768;
    __half* sQ = (__half*)sm;
    __half* sK = (__half*)(sm + 5120);
    __half* sV = (__half*)(sm + 10240);
    float*  sS = (float*)(sm + 15360);
    __half* sP = (__half*)sm;           // overlays Q/K once consumed
    int win = blockIdx.x;
    int head = blockIdx.y * 2 + half_;

    // zero V pad rows 49..63
    for (int idx = t; idx < 15 * 20; idx += 128)
        ((uint32_t*)(sV + 49 * 40))[idx] = 0u;

    const __half* base = g_qkvh + (size_t)win * LL * C3 + head * HDIM;
    const __half2 sc2 = __float2half2_rn(0.17677669529663687f);  // 1/sqrt(32)
    for (int idx = t; idx < LL * 4; idx += 128) {
        int l = idx >> 2, d8 = (idx & 3) * 8;
        const __half* p = base + (size_t)l * C3 + d8;
        uint4 q4 = *(const uint4*)(p);
        uint4 k4 = *(const uint4*)(p + 384);
        uint4 v4 = *(const uint4*)(p + 768);
        __half2* qh = (__half2*)&q4;
        #pragma unroll
        for (int e = 0; e < 4; e++) qh[e] = __hmul2(qh[e], sc2);
        *(uint4*)(sQ + l * 40 + d8) = q4;
        *(uint4*)(sK + l * 40 + d8) = k4;
        *(uint4*)(sV + l * 40 + d8) = v4;
    }
    __syncthreads();

    // ---- S = Q.K^T : local warp lw -> rows 16lw..16lw+15 ----
    {
        wmma::fragment<wmma::accumulator, 16, 16, 16, float> sacc[4];
        #pragma unroll
        for (int n = 0; n < 4; n++) wmma::fill_fragment(sacc[n], 0.0f);
        #pragma unroll
        for (int k = 0; k < 2; k++) {
            wmma::fragment<wmma::matrix_a, 16, 16, 16, __half, wmma::row_major> af;
            wmma::load_matrix_sync(af, sQ + lw * 16 * 40 + k * 16, 40);
            #pragma unroll
            for (int n = 0; n < 4; n++) {
                wmma::fragment<wmma::matrix_b, 16, 16, 16, __half, wmma::col_major> bf;
                wmma::load_matrix_sync(bf, sK + n * 16 * 40 + k * 16, 40);
                wmma::mma_sync(sacc[n], af, bf, sacc[n]);
            }
        }
        #pragma unroll
        for (int n = 0; n < 4; n++)
            wmma::store_matrix_sync(sS + lw * 16 * 68 + n * 16, sacc[n], 68, wmma::mem_row_major);
    }
    __syncthreads();

    // zero P fully (aliases Q/K, now dead)
    #pragma unroll
    for (int q = 0; q < 18; q++) ((uint32_t*)sP)[t + q * 128] = 0u;
    __syncthreads();

    // ---- softmax rows 0..48 (cols 0..48), write P fp16 ----
    bool has2 = lane < 17;
    for (int i = lw; i < LL; i += 4) {
        float a = sS[i * 68 + lane];
        float b = has2 ? sS[i * 68 + lane + 32] : -3.0e38f;
        float m = fmaxf(a, b);
        #pragma unroll
        for (int o = 16; o; o >>= 1) m = fmaxf(m, __shfl_xor_sync(0xffffffffu, m, o));
        float e0 = __expf(a - m);
        float e1 = has2 ? __expf(b - m) : 0.f;
        float sm_ = e0 + e1;
        #pragma unroll
        for (int o = 16; o; o >>= 1) sm_ += __shfl_xor_sync(0xffffffffu, sm_, o);
        float inv = 1.0f / sm_;
        sP[i * 72 + lane] = __float2half(e0 * inv);
        if (has2) sP[i * 72 + lane + 32] = __float2half(e1 * inv);
    }
    __syncthreads();

    // ---- O = P.V : local warp lw -> rows 16lw..16lw+15; out via sS (ldm 36) --
    {
        wmma::fragment<wmma::accumulator, 16, 16, 16, float> oacc[2];
        #pragma unroll
        for (int n = 0; n < 2; n++) wmma::fill_fragment(oacc[n], 0.0f);
        #pragma unroll
        for (int k = 0; k < 4; k++) {
            wmma::fragment<wmma::matrix_a, 16, 16, 16, __half, wmma::row_major> pf;
            wmma::load_matrix_sync(pf, sP + lw * 16 * 72 + k * 16, 72);
            #pragma unroll
            for (int n = 0; n < 2; n++) {
                wmma::fragment<wmma::matrix_b, 16, 16, 16, __half, wmma::row_major> vf;
                wmma::load_matrix_sync(vf, sV + k * 16 * 40 + n * 16, 40);
                wmma::mma_sync(oacc[n], pf, vf, oacc[n]);
            }
        }
        #pragma unroll
        for (int n = 0; n < 2; n++)
            wmma::store_matrix_sync(sS + lw * 16 * 36 + n * 16, oacc[n], 36, wmma::mem_row_major);
    }
    __syncthreads();

    // ---- write O rows 0..48 ----
    for (int idx = t; idx < LL * HDIM; idx += 128) {
        int row = idx >> 5, col = idx & 31;
        g_a[((size_t)win * LL + row) * CC + head * HDIM + col] =
            __float2half(sS[row * 36 + col]);
    }
}

// ---------------- launch ----------------
extern "C" void kernel_launch(void* const* d_in, const int* in_sizes, int n_in,
                              void* d_out, int out_size) {
    const float* x     = (const float*)d_in[0];
    const float* gamma = (const float*)d_in[1];
    const float* beta  = (const float*)d_in[2];
    const float* w_in  = (const float*)d_in[3];
    const float* b_in  = (const float*)d_in[4];
    const float* w_out = (const float*)d_in[5];
    const float* b_out = (const float*)d_in[6];
    float* out = (float*)d_out;

    cudaFuncSetAttribute(gemm_fp16_kernel<0>,
                         cudaFuncAttributeMaxDynamicSharedMemorySize, GSMEM);
    cudaFuncSetAttribute(gemm_fp16_kernel<1>,
                         cudaFuncAttributeMaxDynamicSharedMemorySize, GSMEM);
    cudaFuncSetAttribute(attn_kernel,
                         cudaFuncAttributeMaxDynamicSharedMemorySize, ASMEM);

    wconv_kernel<<<(C3 * CC + 255) / 256, 256>>>(w_in, w_out);
    ln_window_kernel<<<NTOK, 128>>>(x, gamma, beta);
    gemm_fp16_kernel<0><<<dim3(C3 / 128, NTOK / 128), 256, GSMEM>>>(b_in, nullptr, nullptr);
    attn_kernel<<<dim3(NWIN, NHEAD / 2), 256, ASMEM>>>();
    gemm_fp16_kernel<1><<<dim3(CC / 128, NTOK / 128), 256, GSMEM>>>(b_out, x, out);
}

// round 17
// speedup vs baseline: 1.4565x; 1.0413x over previous
#include <cuda_runtime.h>
#include <cuda_fp16.h>
#include <mma.h>
#include <cstdint>
#include <math.h>

using namespace nvcuda;

// ---------------- static problem dims ----------------
#define BB    32
#define HH    56
#define WWD   56
#define CC    384
#define NTOK  (BB * HH * WWD)      // 100352
#define LL    49
#define NWIN  2048
#define C3    1152
#define NHEAD 12
#define HDIM  32

#define TK    32                    // GEMM K-chunk
#define SST   40                    // GEMM smem row stride (fp16)
#define TILEB (128 * SST * 2)       // 10240 B per tile
#define NSTG  3                     // pipeline stages
#define GSMEM (128 * 132 * 4)       // 67584 B dyn (>= NSTG*2*TILEB = 61440)
#define ASMEM (2 * 32768)           // attn dyn smem: two 32KB head regions
#define NWB   1536                  // weight-conversion blocks (589824/384)

// ---------------- scratch (device globals; no allocs allowed) ----------------
__device__ __half g_yh[(size_t)NTOK * CC];    // LN output fp16, window-ordered
__device__ __half g_qkvh[(size_t)NTOK * C3];  // qkv fp16, window-ordered
__device__ __half g_a[(size_t)NTOK * CC];     // attention out fp16
__device__ __half g_wi[(size_t)C3 * CC];      // w_in fp16
__device__ __half g_wo[(size_t)CC * CC];      // w_out fp16

// ---------------- K1: LN + window partition, fused with weight conv ---------
__global__ void prep_kernel(const float* __restrict__ x,
                            const float* __restrict__ gamma,
                            const float* __restrict__ beta,
                            const float* __restrict__ w_in,
                            const float* __restrict__ w_out) {
    int tid = threadIdx.x;              // 128 threads
    if (blockIdx.x >= NTOK) {
        // weight conversion: 384 elems per block
        int wblk = blockIdx.x - NTOK;
        #pragma unroll
        for (int q = 0; q < 3; q++) {
            int i = wblk * 384 + tid + q * 128;
            if (i < C3 * CC) g_wi[i] = __float2half(w_in[i]);
            else {
                int j = i - C3 * CC;    // < CC*CC by construction
                g_wo[j] = __float2half(w_out[j]);
            }
        }
        return;
    }
    int t = blockIdx.x;
    const float* xin = x + (size_t)t * CC;
    float v0 = xin[tid], v1 = xin[tid + 128], v2 = xin[tid + 256];
    float s = v0 + v1 + v2;
    float s2 = v0 * v0 + v1 * v1 + v2 * v2;
    #pragma unroll
    for (int o = 16; o; o >>= 1) {
        s  += __shfl_down_sync(0xffffffffu, s, o);
        s2 += __shfl_down_sync(0xffffffffu, s2, o);
    }
    __shared__ float red[2][4];
    int wid = tid >> 5, lane = tid & 31;
    if (lane == 0) { red[0][wid] = s; red[1][wid] = s2; }
    __syncthreads();
    if (tid == 0) {
        float a = red[0][0] + red[0][1] + red[0][2] + red[0][3];
        float b = red[1][0] + red[1][1] + red[1][2] + red[1][3];
        float mu = a * (1.0f / CC);
        float var = b * (1.0f / CC) - mu * mu;
        red[0][0] = mu;
        red[1][0] = rsqrtf(var + 1e-5f);
    }
    __syncthreads();
    float mu = red[0][0], rs = red[1][0];

    int b_ = t / (HH * WWD);
    int n  = t % (HH * WWD);
    int h = n / WWD, w = n % WWD;
    int wi = h / 7, i = h % 7, wj = w / 7, j = w % 7;
    size_t row = (size_t)((b_ * 64 + wi * 8 + wj) * LL + i * 7 + j) * CC;
    #pragma unroll
    for (int q = 0; q < 3; q++) {
        int c = tid + q * 128;
        float v = (q == 0) ? v0 : (q == 1) ? v1 : v2;
        g_yh[row + c] = __float2half((v - mu) * rs * gamma[c] + beta[c]);
    }
}

// ---------------- cp.async helpers ----------------
__device__ __forceinline__ void cpa16(uint32_t saddr, const void* gptr) {
    asm volatile("cp.async.cg.shared.global [%0], [%1], 16;" :: "r"(saddr), "l"(gptr));
}

// ---------------- K2/K4: fp16 wmma GEMM, 128x128, 3-stage, 1 barrier/chunk --
template <int EPI>
__global__ void __launch_bounds__(256, 2) gemm_fp16_kernel(
        const float* __restrict__ bias,
        const float* __restrict__ resid,
        float* __restrict__ Cout) {
    extern __shared__ __align__(16) char smraw[];
    __half* stage[NSTG][2];
    #pragma unroll
    for (int s = 0; s < NSTG; s++)
        #pragma unroll
        for (int t = 0; t < 2; t++)
            stage[s][t] = (__half*)(smraw + (s * 2 + t) * TILEB);

    const __half* A = (EPI == 0) ? g_yh : g_a;
    const __half* B = (EPI == 0) ? g_wi : g_wo;

    const int tid = threadIdx.x;        // 256 threads, 8 warps
    const int warp = tid >> 5;
    const int wm = warp >> 1;           // rows wm*32..+32
    const int wn = warp & 1;            // cols wn*64..+64
    const int n0 = blockIdx.x * 128;
    const int m0 = blockIdx.y * 128;

    const int r0 = tid >> 1, s0 = (tid & 1) * 2;

    wmma::fragment<wmma::accumulator, 16, 16, 16, float> acc[2][4];
    #pragma unroll
    for (int a = 0; a < 2; a++)
        #pragma unroll
        for (int b = 0; b < 4; b++) wmma::fill_fragment(acc[a][b], 0.0f);

    const int NCH = CC / TK;            // 12

    auto issue_copy = [&](int kc, int st) {
        const int k0 = kc * TK;
        const __half* ga = A + (size_t)(m0 + r0) * CC + k0;
        const __half* gb = B + (size_t)(n0 + r0) * CC + k0;
        uint32_t sa = (uint32_t)__cvta_generic_to_shared(stage[st][0] + r0 * SST + s0 * 8);
        cpa16(sa, ga + s0 * 8);
        cpa16(sa + 16, ga + s0 * 8 + 8);
        uint32_t sb = (uint32_t)__cvta_generic_to_shared(stage[st][1] + r0 * SST + s0 * 8);
        cpa16(sb, gb + s0 * 8);
        cpa16(sb + 16, gb + s0 * 8 + 8);
        asm volatile("cp.async.commit_group;" ::: "memory");
    };

    issue_copy(0, 0);
    issue_copy(1, 1);

    for (int kc = 0; kc < NCH; kc++) {
        const int cur = kc % NSTG;
        if (kc + 1 < NCH) {
            asm volatile("cp.async.wait_group 1;" ::: "memory");
        } else {
            asm volatile("cp.async.wait_group 0;" ::: "memory");
        }
        __syncthreads();                // single barrier per chunk
        if (kc + 2 < NCH) issue_copy(kc + 2, (kc + 2) % NSTG);
        const __half* sA = stage[cur][0];
        const __half* sB = stage[cur][1];
        #pragma unroll
        for (int kk = 0; kk < TK; kk += 16) {
            wmma::fragment<wmma::matrix_a, 16, 16, 16, __half, wmma::row_major> af[2];
            wmma::fragment<wmma::matrix_b, 16, 16, 16, __half, wmma::col_major> bf[4];
            #pragma unroll
            for (int mi = 0; mi < 2; mi++)
                wmma::load_matrix_sync(af[mi], sA + (wm * 32 + mi * 16) * SST + kk, SST);
            #pragma unroll
            for (int ni = 0; ni < 4; ni++)
                wmma::load_matrix_sync(bf[ni], sB + (wn * 64 + ni * 16) * SST + kk, SST);
            #pragma unroll
            for (int mi = 0; mi < 2; mi++)
                #pragma unroll
                for (int ni = 0; ni < 4; ni++)
                    wmma::mma_sync(acc[mi][ni], af[mi], bf[ni], acc[mi][ni]);
        }
    }

    // ---- epilogue: single pass, Cs 128x132 fp32 ----
    float* Cs = (float*)smraw;
    __syncthreads();
    #pragma unroll
    for (int mi = 0; mi < 2; mi++)
        #pragma unroll
        for (int ni = 0; ni < 4; ni++)
            wmma::store_matrix_sync(Cs + (wm * 32 + mi * 16) * 132 + wn * 64 + ni * 16,
                                    acc[mi][ni], 132, wmma::mem_row_major);
    __syncthreads();
    if (EPI == 0) {
        #pragma unroll
        for (int q = 0; q < 32; q++) {
            int idx = tid + q * 256;
            int r = idx >> 6, c2 = (idx & 63) * 2;
            int gcol = n0 + c2;
            float vx = Cs[r * 132 + c2]     + bias[gcol];
            float vy = Cs[r * 132 + c2 + 1] + bias[gcol + 1];
            *(__half2*)(g_qkvh + (size_t)(m0 + r) * C3 + gcol) =
                __floats2half2_rn(vx, vy);
        }
    } else {
        #pragma unroll
        for (int q = 0; q < 64; q++) {
            int idx = tid + q * 256;
            int r = idx >> 7, c = idx & 127;
            int gcol = n0 + c;
            float val = Cs[r * 132 + c] + bias[gcol];
            int m = m0 + r;
            int win = m / LL, l = m % LL;
            int b_ = win >> 6, wr = win & 63;
            int wi = wr >> 3, wj = wr & 7;
            int i = l / 7, j = l % 7;
            size_t orig = (size_t)b_ * (HH * WWD) + (size_t)(wi * 7 + i) * WWD + (wj * 7 + j);
            size_t off = orig * CC + gcol;
            Cout[off] = resid[off] + val;
        }
    }
}

// ---------------- K3: attention, 2 heads per CTA, trimmed zero + interleaved softmax
// per-head region (32768 B): sQ 0..5120, sK 5120..10240, sV 10240..15360,
//   sS 15360..32768 (64x68 fp32); sP aliases [0..9216) after S is built.
__global__ void attn_kernel() {
    extern __shared__ __align__(16) char smbase[];
    int tid = threadIdx.x;              // 256 threads, 8 warps
    int half_ = tid >> 7;               // which head
    int t = tid & 127;
    int lw = (tid >> 5) & 3;            // warp within half
    int lane = tid & 31;
    char* sm = smbase + half_ * 32768;
    __half* sQ = (__half*)sm;
    __half* sK = (__half*)(sm + 5120);
    __half* sV = (__half*)(sm + 10240);
    float*  sS = (float*)(sm + 15360);
    __half* sP = (__half*)sm;           // overlays Q/K once consumed
    int win = blockIdx.x;
    int head = blockIdx.y * 2 + half_;

    // zero V pad rows 49..63
    for (int idx = t; idx < 15 * 20; idx += 128)
        ((uint32_t*)(sV + 49 * 40))[idx] = 0u;

    const __half* base = g_qkvh + (size_t)win * LL * C3 + head * HDIM;
    const __half2 sc2 = __float2half2_rn(0.17677669529663687f);  // 1/sqrt(32)
    for (int idx = t; idx < LL * 4; idx += 128) {
        int l = idx >> 2, d8 = (idx & 3) * 8;
        const __half* p = base + (size_t)l * C3 + d8;
        uint4 q4 = *(const uint4*)(p);
        uint4 k4 = *(const uint4*)(p + 384);
        uint4 v4 = *(const uint4*)(p + 768);
        __half2* qh = (__half2*)&q4;
        #pragma unroll
        for (int e = 0; e < 4; e++) qh[e] = __hmul2(qh[e], sc2);
        *(uint4*)(sQ + l * 40 + d8) = q4;
        *(uint4*)(sK + l * 40 + d8) = k4;
        *(uint4*)(sV + l * 40 + d8) = v4;
    }
    __syncthreads();

    // ---- S = Q.K^T ----
    {
        wmma::fragment<wmma::accumulator, 16, 16, 16, float> sacc[4];
        #pragma unroll
        for (int n = 0; n < 4; n++) wmma::fill_fragment(sacc[n], 0.0f);
        #pragma unroll
        for (int k = 0; k < 2; k++) {
            wmma::fragment<wmma::matrix_a, 16, 16, 16, __half, wmma::row_major> af;
            wmma::load_matrix_sync(af, sQ + lw * 16 * 40 + k * 16, 40);
            #pragma unroll
            for (int n = 0; n < 4; n++) {
                wmma::fragment<wmma::matrix_b, 16, 16, 16, __half, wmma::col_major> bf;
                wmma::load_matrix_sync(bf, sK + n * 16 * 40 + k * 16, 40);
                wmma::mma_sync(sacc[n], af, bf, sacc[n]);
            }
        }
        #pragma unroll
        for (int n = 0; n < 4; n++)
            wmma::store_matrix_sync(sS + lw * 16 * 68 + n * 16, sacc[n], 68, wmma::mem_row_major);
    }
    __syncthreads();                    // S done; Q/K now dead -> sP alias legal

    // zero only P pad rows 49..63 (cols 0..63): 15 rows x 32 u32 = 480 words
    for (int idx = t; idx < 480; idx += 128) {
        int r = 49 + idx / 32, c = idx % 32;
        ((uint32_t*)(sP + r * 72))[c] = 0u;
    }

    // ---- softmax rows 0..48, 2 rows interleaved per warp pass ----
    // covers P cols 0..63 (cols 49..63 get exact 0); rows 49..63 zeroed above.
    {
        int j1 = lane + 32;
        bool v1ok = j1 <= 48;
        #pragma unroll
        for (int g = 0; g < 7; g++) {
            int iA = lw + g * 8;        // rows lw+8g and lw+8g+4
            int iB = iA + 4;
            bool okA = iA < LL, okB = iB < LL;
            int rA = okA ? iA : 0, rB = okB ? iB : 0;
            float aA = sS[rA * 68 + lane];
            float bA = v1ok ? sS[rA * 68 + j1] : -3.0e38f;
            float aB = sS[rB * 68 + lane];
            float bB = v1ok ? sS[rB * 68 + j1] : -3.0e38f;
            float mA = fmaxf(aA, bA), mB = fmaxf(aB, bB);
            #pragma unroll
            for (int o = 16; o; o >>= 1) {
                mA = fmaxf(mA, __shfl_xor_sync(0xffffffffu, mA, o));
                mB = fmaxf(mB, __shfl_xor_sync(0xffffffffu, mB, o));
            }
            float e0A = __expf(aA - mA), e1A = v1ok ? __expf(bA - mA) : 0.f;
            float e0B = __expf(aB - mB), e1B = v1ok ? __expf(bB - mB) : 0.f;
            float sA_ = e0A + e1A, sB_ = e0B + e1B;
            #pragma unroll
            for (int o = 16; o; o >>= 1) {
                sA_ += __shfl_xor_sync(0xffffffffu, sA_, o);
                sB_ += __shfl_xor_sync(0xffffffffu, sB_, o);
            }
            float invA = 1.0f / sA_, invB = 1.0f / sB_;
            if (okA) {
                sP[rA * 72 + lane] = __float2half(e0A * invA);
                sP[rA * 72 + j1]   = __float2half(e1A * invA);   // 0 for j1>48
            }
            if (okB) {
                sP[rB * 72 + lane] = __float2half(e0B * invB);
                sP[rB * 72 + j1]   = __float2half(e1B * invB);
            }
        }
    }
    __syncthreads();

    // ---- O = P.V ----
    {
        wmma::fragment<wmma::accumulator, 16, 16, 16, float> oacc[2];
        #pragma unroll
        for (int n = 0; n < 2; n++) wmma::fill_fragment(oacc[n], 0.0f);
        #pragma unroll
        for (int k = 0; k < 4; k++) {
            wmma::fragment<wmma::matrix_a, 16, 16, 16, __half, wmma::row_major> pf;
            wmma::load_matrix_sync(pf, sP + lw * 16 * 72 + k * 16, 72);
            #pragma unroll
            for (int n = 0; n < 2; n++) {
                wmma::fragment<wmma::matrix_b, 16, 16, 16, __half, wmma::row_major> vf;
                wmma::load_matrix_sync(vf, sV + k * 16 * 40 + n * 16, 40);
                wmma::mma_sync(oacc[n], pf, vf, oacc[n]);
            }
        }
        #pragma unroll
        for (int n = 0; n < 2; n++)
            wmma::store_matrix_sync(sS + lw * 16 * 36 + n * 16, oacc[n], 36, wmma::mem_row_major);
    }
    __syncthreads();

    // ---- write O rows 0..48 ----
    for (int idx = t; idx < LL * HDIM; idx += 128) {
        int row = idx >> 5, col = idx & 31;
        g_a[((size_t)win * LL + row) * CC + head * HDIM + col] =
            __float2half(sS[row * 36 + col]);
    }
}

// ---------------- launch ----------------
extern "C" void kernel_launch(void* const* d_in, const int* in_sizes, int n_in,
                              void* d_out, int out_size) {
    const float* x     = (const float*)d_in[0];
    const float* gamma = (const float*)d_in[1];
    const float* beta  = (const float*)d_in[2];
    const float* w_in  = (const float*)d_in[3];
    const float* b_in  = (const float*)d_in[4];
    const float* w_out = (const float*)d_in[5];
    const float* b_out = (const float*)d_in[6];
    float* out = (float*)d_out;

    cudaFuncSetAttribute(gemm_fp16_kernel<0>,
                         cudaFuncAttributeMaxDynamicSharedMemorySize, GSMEM);
    cudaFuncSetAttribute(gemm_fp16_kernel<1>,
                         cudaFuncAttributeMaxDynamicSharedMemorySize, GSMEM);
    cudaFuncSetAttribute(attn_kernel,
                         cudaFuncAttributeMaxDynamicSharedMemorySize, ASMEM);

    prep_kernel<<<NTOK + NWB, 128>>>(x, gamma, beta, w_in, w_out);
    gemm_fp16_kernel<0><<<dim3(C3 / 128, NTOK / 128), 256, GSMEM>>>(b_in, nullptr, nullptr);
    attn_kernel<<<dim3(NWIN, NHEAD / 2), 256, ASMEM>>>();
    gemm_fp16_kernel<1><<<dim3(CC / 128, NTOK / 128), 256, GSMEM>>>(b_out, x, out);
}